// round 9
// baseline (speedup 1.0000x reference)
#include <cuda_runtime.h>
#include <cuda_bf16.h>

#define EPS 1e-16f
#define W 1024
#define H 1024
#define ROWS 4          // output rows per thread/block
#define TPB 256         // 256 threads * 4 px = 1024 = full row width

// out = (dxf+dyf)*invF - dxf(x-1,y)*invF(x-1,y) - dyf(x,y-1)*invF(x,y-1)
// using G(x,y) = F(x-1,y), H(x,y) = F(x,y-1) on the reflect-padded grid.
__global__ __launch_bounds__(TPB, 5)
void curvature_kernel(const float* __restrict__ u, float* __restrict__ out) {
    const int tile = blockIdx.x;            // b * (H/ROWS) + row-tile
    const int b    = tile >> 8;             // H/ROWS = 256 tiles per image
    const int x0   = (tile & 255) * ROWS;   // first output row
    const int t    = threadIdx.x;
    const int y    = t * 4;                 // first output col (float4 granule)

    const float* ub = u   + (size_t)b * (H * W);
    float*       ob = out + (size_t)b * (H * W);

    // smemR[k][t]   : rows[k][0] (col y of padded row x0-1+k) -> right halo for t-1
    // smemB[k][s]   : B = dyf*invF at padded col (4*s - 1), row x0-1+k
    __shared__ float smemR[ROWS + 1][TPB];
    __shared__ float smemB[ROWS + 1][TPB + 1];

    // ---- 6 row-vectors (padded rows x0-1 .. x0+4), reflect-clamped in x ----
    float rows[ROWS + 2][4];
    #pragma unroll
    for (int m = 0; m < ROWS + 2; ++m) {
        int r = x0 - 1 + m;
        r = (r < 0) ? 1 : ((r >= H) ? (H - 2) : r);
        float4 v = *reinterpret_cast<const float4*>(ub + (size_t)r * W + y);
        rows[m][0] = v.x; rows[m][1] = v.y; rows[m][2] = v.z; rows[m][3] = v.w;
    }

    // ---- publish col-0 halo ----
    #pragma unroll
    for (int k = 0; k <= ROWS; ++k) smemR[k][t] = rows[k][0];
    __syncthreads();

    // ---- pre-pass: col-3 F terms + publish left-products B ----
    const int tp = (t < TPB - 1) ? (t + 1) : t;
    float S3[ROWS + 1], A3[ROWS + 1];
    #pragma unroll
    for (int k = 0; k <= ROWS; ++k) {
        float rg   = smemR[k][tp];
        rg         = (t == TPB - 1) ? rows[k][2] : rg;     // reflect: col W -> W-2
        float dxf3 = rows[k + 1][3] - rows[k][3];
        float dyf3 = rg - rows[k][3];
        float iF3  = rsqrtf(fmaf(dxf3, dxf3, fmaf(dyf3, dyf3, EPS)));
        S3[k] = (dxf3 + dyf3) * iF3;
        A3[k] = dxf3 * iF3;
        smemB[k][t + 1] = dyf3 * iF3;
    }
    if (t == 0) {
        // virtual col -1 == col 1 (reflect): dyf(x,-1) = u[x,0]-u[x,1],
        // dxf(x,-1) = u[x+1,1]-u[x,1]
        #pragma unroll
        for (int k = 0; k <= ROWS; ++k) {
            float dy = rows[k][0] - rows[k][1];
            float dx = rows[k + 1][1] - rows[k][1];
            smemB[k][0] = dy * rsqrtf(fmaf(dx, dx, fmaf(dy, dy, EPS)));
        }
    }
    __syncthreads();

    // ---- main sweep over F-rows k (padded row x0-1+k); emit out row x0+k-1 ----
    float Aprev[4];
    #pragma unroll
    for (int k = 0; k <= ROWS; ++k) {
        float Scur[4], Acur[4], Bcur[3];
        #pragma unroll
        for (int j = 0; j < 3; ++j) {
            float dxf = rows[k + 1][j] - rows[k][j];
            float dyf = rows[k][j + 1] - rows[k][j];
            float iF  = rsqrtf(fmaf(dxf, dxf, fmaf(dyf, dyf, EPS)));
            Scur[j] = (dxf + dyf) * iF;
            Acur[j] = dxf * iF;
            Bcur[j] = dyf * iF;
        }
        Scur[3] = S3[k];
        Acur[3] = A3[k];

        if (k > 0) {
            float Bleft = smemB[k][t];      // padded col y-1, row x0-1+k
            float4 o;
            o.x = Scur[0] - Aprev[0] - Bleft;
            o.y = Scur[1] - Aprev[1] - Bcur[0];
            o.z = Scur[2] - Aprev[2] - Bcur[1];
            o.w = Scur[3] - Aprev[3] - Bcur[2];
            *reinterpret_cast<float4*>(ob + (size_t)(x0 + k - 1) * W + y) = o;
        }
        #pragma unroll
        for (int j = 0; j < 4; ++j) Aprev[j] = Acur[j];
    }
}

extern "C" void kernel_launch(void* const* d_in, const int* in_sizes, int n_in,
                              void* d_out, int out_size) {
    const float* u = (const float*)d_in[0];
    float* out = (float*)d_out;
    const int batch = in_sizes[0] / (H * W);   // 16
    const int blocks = batch * (H / ROWS);     // 4096
    curvature_kernel<<<blocks, TPB>>>(u, out);
}